// round 1
// baseline (speedup 1.0000x reference)
#include <cuda_runtime.h>

// Langevin_2439541424651 — per-element independent 200-step recurrence.
// Streaming problem: ~100MB read (noise) + ~301MB write. HBM-bound.

#define N_PART 1024
#define DX     128
#define STEPS  200
#define ND     (N_PART * DX)          // 131072 independent recurrences
#define TOT_XT ((long)N_PART * STEPS * DX)   // 26,214,400 elems per [N,S,D] tensor

__global__ void __launch_bounds__(256) langevin_kernel(
    const float* __restrict__ x0,      // [N, DX]
    const float* __restrict__ y0,      // [N, DX]  (D_Y == DX == 128)
    const float* __restrict__ mean,    // [DX]
    const float* __restrict__ var,     // [DX]
    const float* __restrict__ gammas,  // [STEPS]
    const float* __restrict__ noise,   // [STEPS, N, DX]
    float* __restrict__ x_tot,         // [N, STEPS, DX]
    float* __restrict__ y_tot,         // [N, STEPS, DX]
    float* __restrict__ out)           // [N, STEPS, DX]
{
    __shared__ float s_g[STEPS];
    __shared__ float s_s[STEPS];

    // Stage per-step constants once per block.
    for (int k = threadIdx.x; k < STEPS; k += blockDim.x) {
        float g = gammas[k];
        s_g[k] = g;
        s_s[k] = sqrtf(2.0f * g);
    }
    __syncthreads();

    int tid = blockIdx.x * blockDim.x + threadIdx.x;   // 0 .. ND-1
    int d = tid & (DX - 1);
    int n = tid >> 7;                                   // DX = 128 = 2^7

    float x  = x0[tid];
    float yv = y0[tid];
    float m  = mean[d];
    float iv = 1.0f / var[d];

    long base = (long)n * STEPS * DX + d;
    const float* __restrict__ zp = noise + tid;

    // t_old = x - c*(x-m), c = gamma/var
    // x_new = t_old + sqrt(2*gamma)*z
    // t_old - t_new = t_old - x_new + c*(x_new - m)
#pragma unroll 4
    for (int k = 0; k < STEPS; ++k) {
        float g = s_g[k];
        float s = s_s[k];
        float z = zp[(long)k * ND];

        float c     = g * iv;
        float t_old = fmaf(-c, x - m, x);
        float xn    = fmaf(s, z, t_old);
        float diff  = fmaf(c, xn - m, t_old - xn);
        x = xn;

        long o = base + (long)k * DX;
        x_tot[o] = xn;
        y_tot[o] = yv;
        out[o]   = diff;
    }
}

__global__ void __launch_bounds__(256) steps_kernel(float* __restrict__ steps_out, int total)
{
    int i = blockIdx.x * blockDim.x + threadIdx.x;
    if (i < total) {
        // layout [N, STEPS, 1]: value = i % STEPS
        int k = i - (i / STEPS) * STEPS;
        steps_out[i] = (float)k;
    }
}

extern "C" void kernel_launch(void* const* d_in, const int* in_sizes, int n_in,
                              void* d_out, int out_size)
{
    const float* x0     = (const float*)d_in[0];
    const float* y0     = (const float*)d_in[1];
    const float* mean   = (const float*)d_in[2];
    const float* var    = (const float*)d_in[3];
    const float* gammas = (const float*)d_in[4];
    const float* noise  = (const float*)d_in[5];

    float* base  = (float*)d_out;
    float* x_tot = base;                 // [N, S, D]
    float* y_tot = base + TOT_XT;        // [N, S, D]
    float* outp  = base + 2 * TOT_XT;    // [N, S, D]
    float* steps = base + 3 * TOT_XT;    // [N, S, 1]

    langevin_kernel<<<ND / 256, 256>>>(x0, y0, mean, var, gammas, noise,
                                       x_tot, y_tot, outp);

    int steps_total = N_PART * STEPS;    // 204800
    steps_kernel<<<(steps_total + 255) / 256, 256>>>(steps, steps_total);
}